// round 17
// baseline (speedup 1.0000x reference)
#include <cuda_runtime.h>
#include <cstdint>

#define H    50
#define G4   200
#define E    4
#define BSZ  512
#define NTH  448
#define NCH  7       // ulonglong2 chunks per K-half
#define HPAD 56

typedef unsigned long long u64;

__device__ __forceinline__ void fma2(u64 &d, u64 a, u64 b) {
    asm("fma.rn.f32x2 %0, %1, %2, %0;" : "+l"(d) : "l"(a), "l"(b));
}
__device__ __forceinline__ float lo32(u64 a){ return __uint_as_float((unsigned)a); }
__device__ __forceinline__ float hi32(u64 a){ return __uint_as_float((unsigned)(a >> 32)); }
__device__ __forceinline__ float hsum2(u64 a){ return lo32(a) + hi32(a); }
__device__ __forceinline__ u64 pk2(float lo, float hi) {
    return ((u64)__float_as_uint(hi) << 32) | (u64)__float_as_uint(lo);
}
__device__ __forceinline__ float sigf(float v) {
    return __fdividef(1.0f, 1.0f + __expf(-v));
}
__device__ __forceinline__ float tanhf_(float v) {
    return 1.0f - __fdividef(2.0f, 1.0f + __expf(2.0f * v));
}

__global__ void __launch_bounds__(NTH, 1) sinelstm_kernel(
    const float* __restrict__ x,
    const float* __restrict__ W_ih1, const float* __restrict__ W_hh1,
    const float* __restrict__ b_ih1, const float* __restrict__ b_hh1,
    const float* __restrict__ W_ih2, const float* __restrict__ W_hh2,
    const float* __restrict__ b_ih2, const float* __restrict__ b_hh2,
    const float* __restrict__ W_lin, const float* __restrict__ b_lin,
    float* __restrict__ out, int T, int TP)
{
    __shared__ __align__(16) float h1s[E][HPAD];
    __shared__ __align__(16) float h2s[E][HPAD];
    __shared__ float g1h[2][E][G4];             // half-split raw partials
    __shared__ float g2h[2][E][G4];
    __shared__ __align__(16) float obuf[E][52];
    __shared__ float outs_s[E];
    __shared__ float xs[2][E][32];              // staged x tiles

    const int  t    = threadIdx.x;
    const int  base = blockIdx.x * E;
    const bool row_ok = (t < 400);
    // warp-segregated halves: warps 0-5 pure hf0, 7-12 pure hf1, warp 6 mixed
    const int  hf   = (t >= 200) ? 1 : 0;
    const int  pr   = t - 200 * hf;

    // ---- register-resident weights: row pr, K-half hf (raw dots only) ----
    u64 w1p[2 * NCH], wa[2 * NCH], wb[2 * NCH];
    {
        #pragma unroll
        for (int p = 0; p < 2 * NCH; p++) {
            int k = 2 * (hf * 2 * NCH + p);
            float a0 = (row_ok && k     < H) ? W_hh1[pr * H + k]     : 0.f;
            float a1 = (row_ok && k + 1 < H) ? W_hh1[pr * H + k + 1] : 0.f;
            w1p[p] = pk2(a0, a1);
            float c0 = (row_ok && k     < H) ? W_ih2[pr * H + k]     : 0.f;
            float c1v= (row_ok && k + 1 < H) ? W_ih2[pr * H + k + 1] : 0.f;
            wa[p] = pk2(c0, c1v);
            float d0 = (row_ok && k     < H) ? W_hh2[pr * H + k]     : 0.f;
            float d1 = (row_ok && k + 1 < H) ? W_hh2[pr * H + k + 1] : 0.f;
            wb[p] = pk2(d0, d1);
        }
    }

    // ---- act roles: t<200 layer1 (ue,uu); 200<=t<400 layer2 ----
    const bool l1t = (t < 200);
    const bool l2t = (t >= 200) && (t < 400);
    const int  ui  = t % 200;
    const int  ue  = ui / 50;
    const int  uu  = ui % 50;
    float cst = 0.f;
    float bgi = 0.f, bgf = 0.f, bgg = 0.f, bgo = 0.f;
    float wxi = 0.f, wxf = 0.f, wxg = 0.f, wxo = 0.f;
    if (l1t) {
        bgi = b_ih1[uu] + b_hh1[uu];
        bgf = b_ih1[uu + H] + b_hh1[uu + H];
        bgg = b_ih1[uu + 2 * H] + b_hh1[uu + 2 * H];
        bgo = b_ih1[uu + 3 * H] + b_hh1[uu + 3 * H];
        wxi = W_ih1[uu];         wxf = W_ih1[uu + H];
        wxg = W_ih1[uu + 2 * H]; wxo = W_ih1[uu + 3 * H];
    }
    if (l2t) {
        bgi = b_ih2[uu] + b_hh2[uu];
        bgf = b_ih2[uu + H] + b_hh2[uu + H];
        bgg = b_ih2[uu + 2 * H] + b_hh2[uu + 2 * H];
        bgo = b_ih2[uu + 3 * H] + b_hh2[uu + 3 * H];
    }
    const float wlin_u = l2t ? __ldg(&W_lin[uu]) : 0.f;
    const float blin   = b_lin[0];

    const bool fin = (t >= 440) && (t < 444);
    const int  fe  = t - 440;
    const bool ldr = (t >= 416);
    const int  li  = t - 416;

    // ---- init shared state + preload x tile 0 ----
    for (int i = t; i < E * HPAD; i += NTH) { ((float*)h1s)[i] = 0.f; ((float*)h2s)[i] = 0.f; }
    for (int i = t; i < E * 52;   i += NTH) ((float*)obuf)[i] = 0.f;
    if (ldr) {
        #pragma unroll
        for (int e = 0; e < E; e++)
            xs[0][e][li] = __ldg(&x[(size_t)(base + e) * T + li]);
    }
    __syncthreads();

    // ---- lambdas ----
    auto dots_all = [&](int s) {   // raw g1(s) + g2(s-1) partials
        #pragma unroll
        for (int e = 0; e < E; e++) {
            const ulonglong2* h1v = (const ulonglong2*)(&h1s[e][hf * 4 * NCH]);
            const ulonglong2* h2v = (const ulonglong2*)(&h2s[e][hf * 4 * NCH]);
            u64 a1 = 0ull, a2 = 0ull, b2 = 0ull;
            #pragma unroll
            for (int q = 0; q < NCH; q++) {
                ulonglong2 hc = h1v[q];
                fma2(a1, w1p[2 * q],     hc.x);
                fma2(a1, w1p[2 * q + 1], hc.y);
                fma2(a2, wa[2 * q],      hc.x);
                fma2(a2, wa[2 * q + 1],  hc.y);
            }
            #pragma unroll
            for (int q = 0; q < NCH; q++) {
                ulonglong2 hc = h2v[q];
                fma2(b2, wb[2 * q],      hc.x);
                fma2(b2, wb[2 * q + 1],  hc.y);
            }
            g1h[hf][e][pr] = hsum2(a1);
            if (s > 0) g2h[hf][e][pr] = hsum2(a2) + hsum2(b2);
        }
    };
    auto act1 = [&](float xv) {
        float gi = g1h[0][ue][uu]         + g1h[1][ue][uu]         + bgi + wxi * xv;
        float gf = g1h[0][ue][H + uu]     + g1h[1][ue][H + uu]     + bgf + wxf * xv;
        float gg = g1h[0][ue][2 * H + uu] + g1h[1][ue][2 * H + uu] + bgg + wxg * xv;
        float go = g1h[0][ue][3 * H + uu] + g1h[1][ue][3 * H + uu] + bgo + wxo * xv;
        cst = sigf(gf) * cst + sigf(gi) * tanhf_(gg);
        h1s[ue][uu] = sigf(go) * tanhf_(cst);
    };
    auto act2 = [&]() {
        float gi = g2h[0][ue][uu]         + g2h[1][ue][uu]         + bgi;
        float gf = g2h[0][ue][H + uu]     + g2h[1][ue][H + uu]     + bgf;
        float gg = g2h[0][ue][2 * H + uu] + g2h[1][ue][2 * H + uu] + bgg;
        float go = g2h[0][ue][3 * H + uu] + g2h[1][ue][3 * H + uu] + bgo;
        cst = sigf(gf) * cst + sigf(gi) * tanhf_(gg);
        float h2 = sigf(go) * tanhf_(cst);
        h2s[ue][uu] = h2;
        obuf[ue][uu] = wlin_u * h2;
    };
    auto finalize_out = [&](int ostep, bool seed) {
        if (fin) {
            const float4* ob = (const float4*)obuf[fe];
            float a0 = 0.f, a1 = 0.f, a2 = 0.f, a3 = 0.f;
            #pragma unroll
            for (int q = 0; q < 13; q += 4) {
                float4 v0 = ob[q];     a0 += v0.x + v0.y + v0.z + v0.w;
                if (q + 1 < 13) { float4 v1 = ob[q + 1]; a1 += v1.x + v1.y + v1.z + v1.w; }
                if (q + 2 < 13) { float4 v2 = ob[q + 2]; a2 += v2.x + v2.y + v2.z + v2.w; }
                if (q + 3 < 13) { float4 v3 = ob[q + 3]; a3 += v3.x + v3.y + v3.z + v3.w; }
            }
            float o = (a0 + a1) + (a2 + a3) + blin;
            out[(size_t)(base + fe) * TP + ostep] = o;
            if (seed) outs_s[fe] = o;
        }
    };

    // ================= main loop: 2 barriers/step =================
    for (int s = 0; s < T; s++) {
        if (row_ok) {
            dots_all(s);
        } else {
            if (ldr && (s & 31) == 0 && s + 32 < T) {
                const int nb = ((s >> 5) & 1) ^ 1;
                #pragma unroll
                for (int e = 0; e < E; e++)
                    xs[nb][e][li] = __ldg(&x[(size_t)(base + e) * T + (s + 32 + li)]);
            }
            if (s >= 2) finalize_out(s - 2, false);
        }
        __syncthreads();   // A
        if (l1t) act1(xs[(s >> 5) & 1][ue][s & 31]);
        else if (l2t && s > 0) act2();
        __syncthreads();   // B
    }

    // ---- epilogue: g2(T-1) -> act2 -> out(T-2), out(T-1), seed feedback ----
    if (row_ok) {
        #pragma unroll
        for (int e = 0; e < E; e++) {
            const ulonglong2* h1v = (const ulonglong2*)(&h1s[e][hf * 4 * NCH]);
            const ulonglong2* h2v = (const ulonglong2*)(&h2s[e][hf * 4 * NCH]);
            u64 a2 = 0ull, b2 = 0ull;
            #pragma unroll
            for (int q = 0; q < NCH; q++) {
                ulonglong2 ha = h1v[q];
                ulonglong2 hb = h2v[q];
                fma2(a2, wa[2 * q],     ha.x);
                fma2(a2, wa[2 * q + 1], ha.y);
                fma2(b2, wb[2 * q],     hb.x);
                fma2(b2, wb[2 * q + 1], hb.y);
            }
            g2h[hf][e][pr] = hsum2(a2) + hsum2(b2);
        }
    } else {
        finalize_out(T - 2, false);
    }
    __syncthreads();
    if (l2t) act2();
    __syncthreads();
    finalize_out(T - 1, true);
    __syncthreads();

    // ================= predict loop: strict ordering =================
    for (int s = T; s < TP; s++) {
        if (row_ok) {
            #pragma unroll
            for (int e = 0; e < E; e++) {
                const ulonglong2* h1v = (const ulonglong2*)(&h1s[e][hf * 4 * NCH]);
                u64 a1 = 0ull;
                #pragma unroll
                for (int q = 0; q < NCH; q++) {
                    ulonglong2 hc = h1v[q];
                    fma2(a1, w1p[2 * q],     hc.x);
                    fma2(a1, w1p[2 * q + 1], hc.y);
                }
                g1h[hf][e][pr] = hsum2(a1);
            }
        }
        __syncthreads();
        if (l1t) act1(outs_s[ue]);
        __syncthreads();
        if (row_ok) {
            #pragma unroll
            for (int e = 0; e < E; e++) {
                const ulonglong2* h1v = (const ulonglong2*)(&h1s[e][hf * 4 * NCH]);
                const ulonglong2* h2v = (const ulonglong2*)(&h2s[e][hf * 4 * NCH]);
                u64 a2 = 0ull, b2 = 0ull;
                #pragma unroll
                for (int q = 0; q < NCH; q++) {
                    ulonglong2 ha = h1v[q];
                    ulonglong2 hb = h2v[q];
                    fma2(a2, wa[2 * q],     ha.x);
                    fma2(a2, wa[2 * q + 1], ha.y);
                    fma2(b2, wb[2 * q],     hb.x);
                    fma2(b2, wb[2 * q + 1], hb.y);
                }
                g2h[hf][e][pr] = hsum2(a2) + hsum2(b2);
            }
        }
        __syncthreads();
        if (l2t) act2();
        __syncthreads();
        finalize_out(s, true);
        __syncthreads();
    }
}

extern "C" void kernel_launch(void* const* d_in, const int* in_sizes, int n_in,
                              void* d_out, int out_size) {
    const float* x     = (const float*)d_in[0];
    const float* W_ih1 = (const float*)d_in[1];
    const float* W_hh1 = (const float*)d_in[2];
    const float* b_ih1 = (const float*)d_in[3];
    const float* b_hh1 = (const float*)d_in[4];
    const float* W_ih2 = (const float*)d_in[5];
    const float* W_hh2 = (const float*)d_in[6];
    const float* b_ih2 = (const float*)d_in[7];
    const float* b_hh2 = (const float*)d_in[8];
    const float* W_lin = (const float*)d_in[9];
    const float* b_lin = (const float*)d_in[10];

    int T  = in_sizes[0] / BSZ;      // 1024
    int TP = out_size   / BSZ;       // 1056

    sinelstm_kernel<<<BSZ / E, NTH>>>(
        x, W_ih1, W_hh1, b_ih1, b_hh1,
        W_ih2, W_hh2, b_ih2, b_hh2,
        W_lin, b_lin, (float*)d_out, T, TP);
}